// round 16
// baseline (speedup 1.0000x reference)
#include <cuda_runtime.h>
#include <cuda_bf16.h>
#include <cstdint>
#include <math.h>

#define NPTS  32768
#define CIN   64
#define NHD   16
#define CQ    1024
#define LNEPS 1e-5f

// ---------------- helpers ----------------
__device__ __forceinline__ uint32_t smem_u32(const void* p) {
    uint32_t a;
    asm("{ .reg .u64 t; cvta.to.shared.u64 t, %1; cvt.u32.u64 %0, t; }" : "=r"(a) : "l"(p));
    return a;
}
__device__ __forceinline__ void ldsm_x4(uint32_t r[4], uint32_t addr) {
    asm volatile("ldmatrix.sync.aligned.m8n8.x4.shared.b16 {%0,%1,%2,%3}, [%4];"
                 : "=r"(r[0]), "=r"(r[1]), "=r"(r[2]), "=r"(r[3]) : "r"(addr));
}
__device__ __forceinline__ void mma_bf16(float c[4], const uint32_t a[4], uint32_t b0, uint32_t b1) {
    asm volatile("mma.sync.aligned.m16n8k16.row.col.f32.bf16.bf16.f32 "
                 "{%0,%1,%2,%3}, {%4,%5,%6,%7}, {%8,%9}, {%0,%1,%2,%3};"
                 : "+f"(c[0]), "+f"(c[1]), "+f"(c[2]), "+f"(c[3])
                 : "r"(a[0]), "r"(a[1]), "r"(a[2]), "r"(a[3]), "r"(b0), "r"(b1));
}
__device__ __forceinline__ uint32_t pkb(__nv_bfloat16 a, __nv_bfloat16 b) {
    return (uint32_t)__bfloat16_as_ushort(a) | ((uint32_t)__bfloat16_as_ushort(b) << 16);
}
#define CP16(dst, src) \
    asm volatile("cp.async.ca.shared.global [%0], [%1], 16;" :: "r"((uint32_t)(dst)), "l"(src))
#define CP_COMMIT() asm volatile("cp.async.commit_group;")
#define CP_WAIT0()  asm volatile("cp.async.wait_group 0;" ::: "memory")
#define CP_WAIT1()  asm volatile("cp.async.wait_group 1;" ::: "memory")

// ---------------- scratch ----------------
__device__ __align__(16) uint32_t g_xfh [NPTS * 64];   // LN(F) bf16 split, [p][word]
__device__ __align__(16) uint32_t g_xmh [NPTS * 64];   // LN(M) bf16 split
__device__ __align__(16) uint32_t g_qmA [NPTS * 1024]; // qm bf16 split, A-fragment layout
__device__ __align__(16) uint32_t g_GtA [CQ * 64];     // [n][word]: [hi | lo]
__device__ __align__(16) uint32_t g_GtB [CQ * 64];     // [n][word]: [lo | hi]
__device__ float    g_u   [CQ];

// ---------------- kernel 0: fused weights G = Wf Wm^T (bf16 split) + u ----------------
__global__ __launch_bounds__(256) void precompute_kernel(
    const float* __restrict__ wf, const float* __restrict__ wm,
    const float* __restrict__ bf)
{
    int h = blockIdx.x;
    __shared__ float wfs[64][65];
    __shared__ float wms[64][65];
    int tid = threadIdx.x;
    for (int idx = tid; idx < 4096; idx += 256) {
        int r = idx >> 6, d = idx & 63;
        wfs[r][d] = wf[r * CQ + h * 64 + d];
        wms[r][d] = wm[r * CQ + h * 64 + d];
    }
    __syncthreads();
    for (int idx = tid; idx < 2048; idx += 256) {
        int i2 = idx >> 6, j = idx & 63;
        float s0 = 0.f, s1 = 0.f;
        #pragma unroll
        for (int d = 0; d < 64; d++) {
            s0 += wfs[2 * i2][d] * wms[j][d];
            s1 += wfs[2 * i2 + 1][d] * wms[j][d];
        }
        __nv_bfloat16 h0 = __float2bfloat16_rn(s0), h1 = __float2bfloat16_rn(s1);
        __nv_bfloat16 l0 = __float2bfloat16_rn(s0 - __bfloat162float(h0));
        __nv_bfloat16 l1 = __float2bfloat16_rn(s1 - __bfloat162float(h1));
        int n = h * 64 + j;
        uint32_t hp = pkb(h0, h1), lp = pkb(l0, l1);
        g_GtA[n * 64 + i2]      = hp;
        g_GtA[n * 64 + 32 + i2] = lp;
        g_GtB[n * 64 + i2]      = lp;
        g_GtB[n * 64 + 32 + i2] = hp;
    }
    if (tid < 64) {
        float s = 0.f;
        #pragma unroll
        for (int d = 0; d < 64; d++) s += wms[tid][d] * bf[h * 64 + d];
        g_u[h * 64 + tid] = s;
    }
}

// ---------------- kernel 1: LayerNorm -> bf16 split rows ----------------
__global__ __launch_bounds__(128) void ln_kernel(
    const float* __restrict__ src,
    const float* __restrict__ gamma, const float* __restrict__ beta,
    int which)
{
    __shared__ float gs[64], bs[64];
    int tid = threadIdx.x;
    if (tid < 64) { gs[tid] = gamma[tid]; bs[tid] = beta[tid]; }
    __syncthreads();

    int p = blockIdx.x * 128 + tid;
    float v[64];
    float mean = 0.f;
    #pragma unroll
    for (int c = 0; c < 64; c++) { v[c] = src[c * NPTS + p]; mean += v[c]; }
    mean *= (1.f / 64.f);
    float var = 0.f;
    #pragma unroll
    for (int c = 0; c < 64; c++) { float d = v[c] - mean; var += d * d; }
    float rstd = rsqrtf(var * (1.f / 64.f) + LNEPS);

    uint32_t* dst = which ? g_xmh : g_xfh;
    #pragma unroll
    for (int c8 = 0; c8 < 64; c8 += 8) {
        uint32_t hw[4], lw[4];
        #pragma unroll
        for (int j = 0; j < 4; j++) {
            int c = c8 + 2 * j;
            float y0 = (v[c] - mean) * rstd * gs[c] + bs[c];
            float y1 = (v[c + 1] - mean) * rstd * gs[c + 1] + bs[c + 1];
            __nv_bfloat16 h0 = __float2bfloat16_rn(y0), h1 = __float2bfloat16_rn(y1);
            __nv_bfloat16 l0 = __float2bfloat16_rn(y0 - __bfloat162float(h0));
            __nv_bfloat16 l1 = __float2bfloat16_rn(y1 - __bfloat162float(h1));
            hw[j] = pkb(h0, h1);
            lw[j] = pkb(l0, l1);
        }
        *(uint4*)&dst[p * 64 + (c8 >> 1)]      = make_uint4(hw[0], hw[1], hw[2], hw[3]);
        *(uint4*)&dst[p * 64 + 32 + (c8 >> 1)] = make_uint4(lw[0], lw[1], lw[2], lw[3]);
    }
}

// ---------------- kernel 2: qm GEMM via mma.sync bf16 (split; lo*lo dropped) ----------------
#define GEMM_SMEM (98304)

__global__ __launch_bounds__(256, 2) void qm_gemm_mma()
{
    extern __shared__ char smg[];
    __shared__ float su[128];
    int tid = threadIdx.x;
    int wid = tid >> 5, lane = tid & 31;
    int n0 = blockIdx.x * 128;
    int h0 = n0 >> 6;
    int p0 = blockIdx.y * 512;
    int wm = wid & 1, wn = wid >> 1;

    if (tid < 128) su[tid] = g_u[n0 + tid];

    uint32_t smb = smem_u32(smg);
    const uint4* xf4 = (const uint4*)g_xfh;
    const uint4* GA  = (const uint4*)g_GtA;
    const uint4* GB  = (const uint4*)g_GtB;

    #pragma unroll
    for (int i = tid; i < 2048; i += 256) {
        int r = i >> 4, c = i & 15;
        uint32_t dst = r * 256 + ((c ^ (r & 7)) << 4);
        CP16(smb + 32768 + dst, &GA[(n0 + r) * 16 + c]);
        CP16(smb + 65536 + dst, &GB[(n0 + r) * 16 + c]);
    }
    #pragma unroll
    for (int i = tid; i < 1024; i += 256) {
        int r = i >> 4, c = i & 15;
        uint32_t dst = r * 256 + ((c ^ (r & 7)) << 4);
        CP16(smb + dst, &xf4[(p0 + r) * 16 + c]);
    }
    CP_COMMIT();

    int arow = wm * 32 + (lane & 15);
    int ach  = lane >> 4;
    int brow = wn * 32 + (lane & 7) + ((lane >> 4) << 3);
    int bch  = (lane >> 3) & 1;
    int g = lane >> 2, t4 = lane & 3;

    int hh = wn >> 1;
    int h  = h0 + hh;
    int ln = (h & 7) * 4 + t4;
    int hb = h >> 3;
    int cc = wn & 1;
    int baseoff = ln * 32 + hb * 16 + cc * 4;

    #pragma unroll 1
    for (int t = 0; t < 8; t++) {
        __syncthreads();
        if (t < 7) {
            uint32_t abase = ((t + 1) & 1) ? 16384u : 0u;
            int pr = p0 + (t + 1) * 64;
            #pragma unroll
            for (int i = tid; i < 1024; i += 256) {
                int r = i >> 4, c = i & 15;
                uint32_t dst = abase + r * 256 + ((c ^ (r & 7)) << 4);
                CP16(smb + dst, &xf4[(pr + r) * 16 + c]);
            }
            CP_COMMIT();
            CP_WAIT1();
        } else {
            CP_WAIT0();
        }
        __syncthreads();

        uint32_t abase = (t & 1) ? 16384u : 0u;
        float acc[2][4][4];
        #pragma unroll
        for (int mi = 0; mi < 2; mi++)
            #pragma unroll
            for (int ni = 0; ni < 4; ni++)
                #pragma unroll
                for (int e = 0; e < 4; e++) acc[mi][ni][e] = 0.f;

        #pragma unroll
        for (int s = 0; s < 12; s++) {
            int kk = (s < 4) ? s : (s - 4);
            uint32_t boff = (s < 4) ? 32768u : 65536u;
            uint32_t a[2][4];
            #pragma unroll
            for (int mi = 0; mi < 2; mi++) {
                int row = arow + mi * 16;
                int ch  = kk * 2 + ach;
                ldsm_x4(a[mi], smb + abase + row * 256 + ((ch ^ (row & 7)) << 4));
            }
            uint32_t b[2][4];
            #pragma unroll
            for (int nj = 0; nj < 2; nj++) {
                int row = brow + nj * 16;
                int ch  = kk * 2 + bch;
                ldsm_x4(b[nj], smb + boff + row * 256 + ((ch ^ (row & 7)) << 4));
            }
            #pragma unroll
            for (int mi = 0; mi < 2; mi++)
                #pragma unroll
                for (int nj = 0; nj < 2; nj++) {
                    mma_bf16(acc[mi][2 * nj + 0], a[mi], b[nj][0], b[nj][1]);
                    mma_bf16(acc[mi][2 * nj + 1], a[mi], b[nj][2], b[nj][3]);
                }
        }

        #pragma unroll
        for (int mi = 0; mi < 2; mi++) {
            int pA = p0 + t * 64 + wm * 32 + mi * 16 + g;
            uint32_t ahw[4], alw[4], bhw[4], blw[4];
            #pragma unroll
            for (int ni = 0; ni < 4; ni++) {
                int nl = wn * 32 + ni * 8 + 2 * t4;
                float u0 = su[nl], u1 = su[nl + 1];
                float v0 = acc[mi][ni][0] + u0, v1 = acc[mi][ni][1] + u1;
                float v2 = acc[mi][ni][2] + u0, v3 = acc[mi][ni][3] + u1;
                uint32_t hb0 = __float_as_uint(v0) & 0xFFFF0000u;
                uint32_t hb1 = __float_as_uint(v1) & 0xFFFF0000u;
                uint32_t hb2 = __float_as_uint(v2) & 0xFFFF0000u;
                uint32_t hb3 = __float_as_uint(v3) & 0xFFFF0000u;
                float l0 = v0 - __uint_as_float(hb0);
                float l1 = v1 - __uint_as_float(hb1);
                float l2 = v2 - __uint_as_float(hb2);
                float l3 = v3 - __uint_as_float(hb3);
                ahw[ni] = __byte_perm(hb0, hb1, 0x7632);
                bhw[ni] = __byte_perm(hb2, hb3, 0x7632);
                alw[ni] = __byte_perm(__float_as_uint(l0) + 0x8000u,
                                      __float_as_uint(l1) + 0x8000u, 0x7632);
                blw[ni] = __byte_perm(__float_as_uint(l2) + 0x8000u,
                                      __float_as_uint(l3) + 0x8000u, 0x7632);
            }
            *(uint4*)&g_qmA[(long)pA * 1024 + baseoff]           = make_uint4(ahw[0], ahw[1], ahw[2], ahw[3]);
            *(uint4*)&g_qmA[(long)pA * 1024 + baseoff + 8]       = make_uint4(alw[0], alw[1], alw[2], alw[3]);
            *(uint4*)&g_qmA[(long)(pA + 8) * 1024 + baseoff]     = make_uint4(bhw[0], bhw[1], bhw[2], bhw[3]);
            *(uint4*)&g_qmA[(long)(pA + 8) * 1024 + baseoff + 8] = make_uint4(blw[0], blw[1], blw[2], blw[3]);
        }
    }
}

// ---------------- kernel 3: HMMA neighborhood attention (512 thr, <=128 regs) ----------------
// Tables in smem (rpbP padded stride 33, pads = -1e30 so exp masks itself);
// single accumulator chain; A-frag prefetch retained.
#define TSC 17
#define YSC 579
#define ZSC 2321
#define SCRC 9283
#define HALO_BYTES (9303 * 16)

__global__ __launch_bounds__(512) void attn_kernel(
    const float* __restrict__ rpb, float* __restrict__ out)
{
    extern __shared__ uint4 halo4[];
    __shared__ float rpbP[16 * 33];
    __shared__ float4 wv4[32];
    int tid = threadIdx.x;
    int z0 = (blockIdx.x >> 4) * 2;
    int y0 = (blockIdx.x & 15) * 2;

    for (int i = tid; i < 512; i += 512) {
        int h = i >> 5, o = i & 31;
        rpbP[h * 33 + o] = (o < 27) ? rpb[h * 27 + o] : -1e30f;
    }
    if (tid < 32) {
        int o = tid;
        if (o < 27) {
            int dz = o / 9, rr = o - dz * 9, dy = rr / 3, dx = rr - dy * 3;
            wv4[o] = make_float4((float)(dz - 1), (float)(dy - 1), (float)(dx - 1), 0.f);
        } else {
            wv4[o] = make_float4(0.f, 0.f, 0.f, 0.f);
        }
    }

    const uint4* xmh4 = (const uint4*)g_xmh;
    for (int i = tid; i < 8704; i += 512) {
        int pos = i >> 4, c = i & 15;
        int z = pos / 136;
        int r = pos - z * 136;
        int y = r / 34;
        int t = r - y * 34;
        int gz = z0 - 1 + z, gy = y0 - 1 + y, gt = t - 1;
        uint4 v = make_uint4(0, 0, 0, 0);
        if ((unsigned)gz < 32u && (unsigned)gy < 32u && (unsigned)gt < 32u)
            v = xmh4[(gz * 1024 + gy * 32 + gt) * 16 + c];
        halo4[z * ZSC + y * YSC + t * TSC + c] = v;
    }
    for (int i = tid; i < 20; i += 512) halo4[SCRC + i] = make_uint4(0, 0, 0, 0);
    __syncthreads();

    int warp = tid >> 5, lane = tid & 31;
    int pz = warp & 1, py = (warp >> 1) & 1, tq = warp >> 2;
    int g = lane >> 2, t4 = lane & 3;
    int ob2 = 2 * t4;

    int orow  = (lane & 7) + ((lane >> 4) << 3);
    int bhalf = (lane >> 3) & 1;
    int brel[2], bsel[2];
    #pragma unroll
    for (int ng = 0; ng < 2; ng++) {
        int o = orow + ng * 16;
        if (o < 27) {
            int dz = o / 9, rr = o - dz * 9, dy = rr / 3, dx = rr - dy * 3;
            brel[ng] = dz * ZSC + dy * YSC + dx * TSC;
            bsel[ng] = 1;
        } else {
            brel[ng] = SCRC + (o - 27);
            bsel[ng] = 0;
        }
    }
    uint32_t halob = smem_u32(halo4);

    const uint4* qmA4 = (const uint4*)g_qmA;
    int gp0 = (z0 + pz) * 1024 + (y0 + py) * 32 + tq * 8;
    int pb0 = pz * ZSC + py * YSC + (tq * 8) * TSC;

    uint4 A4[8], A4n[8];
    {
        const uint4* ap = &qmA4[((long)gp0 * 32 + lane) * 8];
        #pragma unroll
        for (int j = 0; j < 8; j++) A4[j] = ap[j];
    }

    #pragma unroll 1
    for (int i16 = 0; i16 < 8; i16++) {
        int gp = gp0 + i16;
        int pbase = pb0 + i16 * TSC;

        if (i16 < 7) {
            const uint4* ap = &qmA4[((long)(gp + 1) * 32 + lane) * 8];
            #pragma unroll
            for (int j = 0; j < 8; j++) A4n[j] = ap[j];
        }

        int basech0 = bsel[0] * pbase + brel[0] + bhalf;
        int basech1 = bsel[1] * pbase + brel[1] + bhalf;

        float acc[4][4];
        #pragma unroll
        for (int nt = 0; nt < 4; nt++)
            #pragma unroll
            for (int e = 0; e < 4; e++) acc[nt][e] = 0.f;

        const uint32_t* aw = (const uint32_t*)A4;
        #pragma unroll
        for (int kc = 0; kc < 4; kc++) {
            uint32_t bq[2][4], bq4[2][4];
            ldsm_x4(bq[0],  halob + (uint32_t)(basech0 + kc * 2) * 16u);
            ldsm_x4(bq[1],  halob + (uint32_t)(basech1 + kc * 2) * 16u);
            ldsm_x4(bq4[0], halob + (uint32_t)(basech0 + (kc + 4) * 2) * 16u);
            ldsm_x4(bq4[1], halob + (uint32_t)(basech1 + (kc + 4) * 2) * 16u);

            int u  = kc >> 1;
            int c0 = 2 * (kc & 1);
            uint32_t ah[4], al[4];
            ah[0] = aw[u * 4 + c0];           ah[1] = aw[(4 + u) * 4 + c0];
            ah[2] = aw[u * 4 + c0 + 1];       ah[3] = aw[(4 + u) * 4 + c0 + 1];
            int ul = 2 + u;
            al[0] = aw[ul * 4 + c0];          al[1] = aw[(4 + ul) * 4 + c0];
            al[2] = aw[ul * 4 + c0 + 1];      al[3] = aw[(4 + ul) * 4 + c0 + 1];
            #pragma unroll
            for (int nt = 0; nt < 4; nt++) {
                int ng = nt >> 1, hf = (nt & 1) * 2;
                mma_bf16(acc[nt], ah, bq[ng][hf],  bq[ng][hf + 1]);    // hi*hi
                mma_bf16(acc[nt], ah, bq4[ng][hf], bq4[ng][hf + 1]);   // hi*lo
                mma_bf16(acc[nt], al, bq[ng][hf],  bq[ng][hf + 1]);    // lo*hi
            }
        }

        float S0 = 0.f, Z0 = 0.f, Y0 = 0.f, T0 = 0.f;
        float S1 = 0.f, Z1 = 0.f, Y1 = 0.f, T1 = 0.f;
        #pragma unroll
        for (int i = 0; i < 8; i++) {
            int nt = i >> 1, j = i & 1;
            int o = nt * 8 + ob2 + j;
            float e0 = __expf(acc[nt][j]     + rpbP[g * 33 + o]);
            float e1 = __expf(acc[nt][2 + j] + rpbP[(g + 8) * 33 + o]);
            float4 w = wv4[o];
            S0 += e0; Z0 += e0 * w.x; Y0 += e0 * w.y; T0 += e0 * w.z;
            S1 += e1; Z1 += e1 * w.x; Y1 += e1 * w.y; T1 += e1 * w.z;
        }
        #pragma unroll
        for (int m = 1; m < 4; m <<= 1) {
            S0 += __shfl_xor_sync(0xffffffffu, S0, m);
            Z0 += __shfl_xor_sync(0xffffffffu, Z0, m);
            Y0 += __shfl_xor_sync(0xffffffffu, Y0, m);
            T0 += __shfl_xor_sync(0xffffffffu, T0, m);
            S1 += __shfl_xor_sync(0xffffffffu, S1, m);
            Z1 += __shfl_xor_sync(0xffffffffu, Z1, m);
            Y1 += __shfl_xor_sync(0xffffffffu, Y1, m);
            T1 += __shfl_xor_sync(0xffffffffu, T1, m);
        }
        if (t4 == 0) {
            float i0 = 1.f / S0, i1 = 1.f / S1;
            out[(g * 3 + 0) * NPTS + gp] = Z0 * i0;
            out[(g * 3 + 1) * NPTS + gp] = Y0 * i0;
            out[(g * 3 + 2) * NPTS + gp] = T0 * i0;
            out[((g + 8) * 3 + 0) * NPTS + gp] = Z1 * i1;
            out[((g + 8) * 3 + 1) * NPTS + gp] = Y1 * i1;
            out[((g + 8) * 3 + 2) * NPTS + gp] = T1 * i1;
        }

        #pragma unroll
        for (int j = 0; j < 8; j++) A4[j] = A4n[j];
    }
}

// ---------------- launch ----------------
extern "C" void kernel_launch(void* const* d_in, const int* in_sizes, int n_in,
                              void* d_out, int out_size)
{
    const float* F       = (const float*)d_in[0];
    const float* M       = (const float*)d_in[1];
    const float* gamma_f = (const float*)d_in[2];
    const float* beta_f  = (const float*)d_in[3];
    const float* w_f     = (const float*)d_in[4];
    const float* b_f     = (const float*)d_in[5];
    const float* gamma_m = (const float*)d_in[6];
    const float* beta_m  = (const float*)d_in[7];
    const float* w_m     = (const float*)d_in[8];
    /* b_m (d_in[9]) is softmax-invariant and drops out */
    const float* rpb     = (const float*)d_in[10];
    float* out = (float*)d_out;

    precompute_kernel<<<16, 256>>>(w_f, w_m, b_f);
    ln_kernel<<<NPTS / 128, 128>>>(F, gamma_f, beta_f, 0);
    ln_kernel<<<NPTS / 128, 128>>>(M, gamma_m, beta_m, 1);

    cudaFuncSetAttribute(qm_gemm_mma, cudaFuncAttributeMaxDynamicSharedMemorySize, GEMM_SMEM);
    qm_gemm_mma<<<dim3(8, 64), 256, GEMM_SMEM>>>();

    cudaFuncSetAttribute(attn_kernel, cudaFuncAttributeMaxDynamicSharedMemorySize, HALO_BYTES);
    attn_kernel<<<256, 512, HALO_BYTES>>>(rpb, out);
}

// round 17
// speedup vs baseline: 1.0606x; 1.0606x over previous
#include <cuda_runtime.h>
#include <cuda_bf16.h>
#include <cstdint>
#include <math.h>

#define NPTS  32768
#define CIN   64
#define NHD   16
#define CQ    1024
#define LNEPS 1e-5f

// ---------------- helpers ----------------
__device__ __forceinline__ uint32_t smem_u32(const void* p) {
    uint32_t a;
    asm("{ .reg .u64 t; cvta.to.shared.u64 t, %1; cvt.u32.u64 %0, t; }" : "=r"(a) : "l"(p));
    return a;
}
__device__ __forceinline__ void ldsm_x4(uint32_t r[4], uint32_t addr) {
    asm volatile("ldmatrix.sync.aligned.m8n8.x4.shared.b16 {%0,%1,%2,%3}, [%4];"
                 : "=r"(r[0]), "=r"(r[1]), "=r"(r[2]), "=r"(r[3]) : "r"(addr));
}
__device__ __forceinline__ void mma_bf16(float c[4], const uint32_t a[4], uint32_t b0, uint32_t b1) {
    asm volatile("mma.sync.aligned.m16n8k16.row.col.f32.bf16.bf16.f32 "
                 "{%0,%1,%2,%3}, {%4,%5,%6,%7}, {%8,%9}, {%0,%1,%2,%3};"
                 : "+f"(c[0]), "+f"(c[1]), "+f"(c[2]), "+f"(c[3])
                 : "r"(a[0]), "r"(a[1]), "r"(a[2]), "r"(a[3]), "r"(b0), "r"(b1));
}
__device__ __forceinline__ uint32_t pkb(__nv_bfloat16 a, __nv_bfloat16 b) {
    return (uint32_t)__bfloat16_as_ushort(a) | ((uint32_t)__bfloat16_as_ushort(b) << 16);
}
#define CP16(dst, src) \
    asm volatile("cp.async.ca.shared.global [%0], [%1], 16;" :: "r"((uint32_t)(dst)), "l"(src))
#define CP_COMMIT() asm volatile("cp.async.commit_group;")
#define CP_WAIT0()  asm volatile("cp.async.wait_group 0;" ::: "memory")
#define CP_WAIT1()  asm volatile("cp.async.wait_group 1;" ::: "memory")

// ---------------- scratch ----------------
__device__ __align__(16) uint32_t g_xfh [NPTS * 64];   // LN(F) bf16 split, [p][word]
__device__ __align__(16) uint32_t g_xmh [NPTS * 64];   // LN(M) bf16 split
__device__ __align__(16) uint32_t g_qmA [NPTS * 1024]; // qm bf16 split, A-fragment layout
__device__ __align__(16) uint32_t g_GtA [CQ * 64];     // [n][word]: [hi | lo]
__device__ __align__(16) uint32_t g_GtB [CQ * 64];     // [n][word]: [lo | hi]
__device__ float    g_u   [CQ];

// ---------------- kernel 0: fused weights G = Wf Wm^T (bf16 split) + u ----------------
__global__ __launch_bounds__(256) void precompute_kernel(
    const float* __restrict__ wf, const float* __restrict__ wm,
    const float* __restrict__ bf)
{
    int h = blockIdx.x;
    __shared__ float wfs[64][65];
    __shared__ float wms[64][65];
    int tid = threadIdx.x;
    for (int idx = tid; idx < 4096; idx += 256) {
        int r = idx >> 6, d = idx & 63;
        wfs[r][d] = wf[r * CQ + h * 64 + d];
        wms[r][d] = wm[r * CQ + h * 64 + d];
    }
    __syncthreads();
    for (int idx = tid; idx < 2048; idx += 256) {
        int i2 = idx >> 6, j = idx & 63;
        float s0 = 0.f, s1 = 0.f;
        #pragma unroll
        for (int d = 0; d < 64; d++) {
            s0 += wfs[2 * i2][d] * wms[j][d];
            s1 += wfs[2 * i2 + 1][d] * wms[j][d];
        }
        __nv_bfloat16 h0 = __float2bfloat16_rn(s0), h1 = __float2bfloat16_rn(s1);
        __nv_bfloat16 l0 = __float2bfloat16_rn(s0 - __bfloat162float(h0));
        __nv_bfloat16 l1 = __float2bfloat16_rn(s1 - __bfloat162float(h1));
        int n = h * 64 + j;
        uint32_t hp = pkb(h0, h1), lp = pkb(l0, l1);
        g_GtA[n * 64 + i2]      = hp;
        g_GtA[n * 64 + 32 + i2] = lp;
        g_GtB[n * 64 + i2]      = lp;
        g_GtB[n * 64 + 32 + i2] = hp;
    }
    if (tid < 64) {
        float s = 0.f;
        #pragma unroll
        for (int d = 0; d < 64; d++) s += wms[tid][d] * bf[h * 64 + d];
        g_u[h * 64 + tid] = s;
    }
}

// ---------------- kernel 1: LayerNorm -> bf16 split rows ----------------
__global__ __launch_bounds__(128) void ln_kernel(
    const float* __restrict__ src,
    const float* __restrict__ gamma, const float* __restrict__ beta,
    int which)
{
    __shared__ float gs[64], bs[64];
    int tid = threadIdx.x;
    if (tid < 64) { gs[tid] = gamma[tid]; bs[tid] = beta[tid]; }
    __syncthreads();

    int p = blockIdx.x * 128 + tid;
    float v[64];
    float mean = 0.f;
    #pragma unroll
    for (int c = 0; c < 64; c++) { v[c] = src[c * NPTS + p]; mean += v[c]; }
    mean *= (1.f / 64.f);
    float var = 0.f;
    #pragma unroll
    for (int c = 0; c < 64; c++) { float d = v[c] - mean; var += d * d; }
    float rstd = rsqrtf(var * (1.f / 64.f) + LNEPS);

    uint32_t* dst = which ? g_xmh : g_xfh;
    #pragma unroll
    for (int c8 = 0; c8 < 64; c8 += 8) {
        uint32_t hw[4], lw[4];
        #pragma unroll
        for (int j = 0; j < 4; j++) {
            int c = c8 + 2 * j;
            float y0 = (v[c] - mean) * rstd * gs[c] + bs[c];
            float y1 = (v[c + 1] - mean) * rstd * gs[c + 1] + bs[c + 1];
            __nv_bfloat16 h0 = __float2bfloat16_rn(y0), h1 = __float2bfloat16_rn(y1);
            __nv_bfloat16 l0 = __float2bfloat16_rn(y0 - __bfloat162float(h0));
            __nv_bfloat16 l1 = __float2bfloat16_rn(y1 - __bfloat162float(h1));
            hw[j] = pkb(h0, h1);
            lw[j] = pkb(l0, l1);
        }
        *(uint4*)&dst[p * 64 + (c8 >> 1)]      = make_uint4(hw[0], hw[1], hw[2], hw[3]);
        *(uint4*)&dst[p * 64 + 32 + (c8 >> 1)] = make_uint4(lw[0], lw[1], lw[2], lw[3]);
    }
}

// ---------------- kernel 2: qm GEMM via mma.sync bf16 (R16: bit-trick epilogue) ----------------
#define GEMM_SMEM (98304)

__global__ __launch_bounds__(256, 2) void qm_gemm_mma()
{
    extern __shared__ char smg[];
    __shared__ float su[128];
    int tid = threadIdx.x;
    int wid = tid >> 5, lane = tid & 31;
    int n0 = blockIdx.x * 128;
    int h0 = n0 >> 6;
    int p0 = blockIdx.y * 512;
    int wm = wid & 1, wn = wid >> 1;

    if (tid < 128) su[tid] = g_u[n0 + tid];

    uint32_t smb = smem_u32(smg);
    const uint4* xf4 = (const uint4*)g_xfh;
    const uint4* GA  = (const uint4*)g_GtA;
    const uint4* GB  = (const uint4*)g_GtB;

    #pragma unroll
    for (int i = tid; i < 2048; i += 256) {
        int r = i >> 4, c = i & 15;
        uint32_t dst = r * 256 + ((c ^ (r & 7)) << 4);
        CP16(smb + 32768 + dst, &GA[(n0 + r) * 16 + c]);
        CP16(smb + 65536 + dst, &GB[(n0 + r) * 16 + c]);
    }
    #pragma unroll
    for (int i = tid; i < 1024; i += 256) {
        int r = i >> 4, c = i & 15;
        uint32_t dst = r * 256 + ((c ^ (r & 7)) << 4);
        CP16(smb + dst, &xf4[(p0 + r) * 16 + c]);
    }
    CP_COMMIT();

    int arow = wm * 32 + (lane & 15);
    int ach  = lane >> 4;
    int brow = wn * 32 + (lane & 7) + ((lane >> 4) << 3);
    int bch  = (lane >> 3) & 1;
    int g = lane >> 2, t4 = lane & 3;

    int hh = wn >> 1;
    int h  = h0 + hh;
    int ln = (h & 7) * 4 + t4;
    int hb = h >> 3;
    int cc = wn & 1;
    int baseoff = ln * 32 + hb * 16 + cc * 4;

    #pragma unroll 1
    for (int t = 0; t < 8; t++) {
        __syncthreads();
        if (t < 7) {
            uint32_t abase = ((t + 1) & 1) ? 16384u : 0u;
            int pr = p0 + (t + 1) * 64;
            #pragma unroll
            for (int i = tid; i < 1024; i += 256) {
                int r = i >> 4, c = i & 15;
                uint32_t dst = abase + r * 256 + ((c ^ (r & 7)) << 4);
                CP16(smb + dst, &xf4[(pr + r) * 16 + c]);
            }
            CP_COMMIT();
            CP_WAIT1();
        } else {
            CP_WAIT0();
        }
        __syncthreads();

        uint32_t abase = (t & 1) ? 16384u : 0u;
        float acc[2][4][4];
        #pragma unroll
        for (int mi = 0; mi < 2; mi++)
            #pragma unroll
            for (int ni = 0; ni < 4; ni++)
                #pragma unroll
                for (int e = 0; e < 4; e++) acc[mi][ni][e] = 0.f;

        #pragma unroll
        for (int s = 0; s < 12; s++) {
            int kk = (s < 4) ? s : (s - 4);
            uint32_t boff = (s < 4) ? 32768u : 65536u;
            uint32_t a[2][4];
            #pragma unroll
            for (int mi = 0; mi < 2; mi++) {
                int row = arow + mi * 16;
                int ch  = kk * 2 + ach;
                ldsm_x4(a[mi], smb + abase + row * 256 + ((ch ^ (row & 7)) << 4));
            }
            uint32_t b[2][4];
            #pragma unroll
            for (int nj = 0; nj < 2; nj++) {
                int row = brow + nj * 16;
                int ch  = kk * 2 + bch;
                ldsm_x4(b[nj], smb + boff + row * 256 + ((ch ^ (row & 7)) << 4));
            }
            #pragma unroll
            for (int mi = 0; mi < 2; mi++)
                #pragma unroll
                for (int nj = 0; nj < 2; nj++) {
                    mma_bf16(acc[mi][2 * nj + 0], a[mi], b[nj][0], b[nj][1]);
                    mma_bf16(acc[mi][2 * nj + 1], a[mi], b[nj][2], b[nj][3]);
                }
        }

        #pragma unroll
        for (int mi = 0; mi < 2; mi++) {
            int pA = p0 + t * 64 + wm * 32 + mi * 16 + g;
            uint32_t ahw[4], alw[4], bhw[4], blw[4];
            #pragma unroll
            for (int ni = 0; ni < 4; ni++) {
                int nl = wn * 32 + ni * 8 + 2 * t4;
                float u0 = su[nl], u1 = su[nl + 1];
                float v0 = acc[mi][ni][0] + u0, v1 = acc[mi][ni][1] + u1;
                float v2 = acc[mi][ni][2] + u0, v3 = acc[mi][ni][3] + u1;
                uint32_t hb0 = __float_as_uint(v0) & 0xFFFF0000u;
                uint32_t hb1 = __float_as_uint(v1) & 0xFFFF0000u;
                uint32_t hb2 = __float_as_uint(v2) & 0xFFFF0000u;
                uint32_t hb3 = __float_as_uint(v3) & 0xFFFF0000u;
                float l0 = v0 - __uint_as_float(hb0);
                float l1 = v1 - __uint_as_float(hb1);
                float l2 = v2 - __uint_as_float(hb2);
                float l3 = v3 - __uint_as_float(hb3);
                ahw[ni] = __byte_perm(hb0, hb1, 0x7632);
                bhw[ni] = __byte_perm(hb2, hb3, 0x7632);
                alw[ni] = __byte_perm(__float_as_uint(l0) + 0x8000u,
                                      __float_as_uint(l1) + 0x8000u, 0x7632);
                blw[ni] = __byte_perm(__float_as_uint(l2) + 0x8000u,
                                      __float_as_uint(l3) + 0x8000u, 0x7632);
            }
            *(uint4*)&g_qmA[(long)pA * 1024 + baseoff]           = make_uint4(ahw[0], ahw[1], ahw[2], ahw[3]);
            *(uint4*)&g_qmA[(long)pA * 1024 + baseoff + 8]       = make_uint4(alw[0], alw[1], alw[2], alw[3]);
            *(uint4*)&g_qmA[(long)(pA + 8) * 1024 + baseoff]     = make_uint4(bhw[0], bhw[1], bhw[2], bhw[3]);
            *(uint4*)&g_qmA[(long)(pA + 8) * 1024 + baseoff + 8] = make_uint4(blw[0], blw[1], blw[2], blw[3]);
        }
    }
}

// ---------------- kernel 3: HMMA neighborhood attention (exact R14 best) ----------------
// 256 threads, 8 warps, 16 points/warp, A-frag prefetch, dual accumulators,
// interleaved ldsm (low-reg), per-lane register tables.
#define TSC 17
#define YSC 579
#define ZSC 2321
#define SCRC 9283
#define HALO_BYTES (9303 * 16)

__global__ __launch_bounds__(256) void attn_kernel(
    const float* __restrict__ rpb, float* __restrict__ out)
{
    extern __shared__ uint4 halo4[];
    __shared__ float rpb_s[NHD * 27];
    int tid = threadIdx.x;
    int z0 = (blockIdx.x >> 4) * 2;
    int y0 = (blockIdx.x & 15) * 2;

    for (int i = tid; i < NHD * 27; i += 256) rpb_s[i] = rpb[i];

    const uint4* xmh4 = (const uint4*)g_xmh;
    for (int i = tid; i < 8704; i += 256) {
        int pos = i >> 4, c = i & 15;
        int z = pos / 136;
        int r = pos - z * 136;
        int y = r / 34;
        int t = r - y * 34;
        int gz = z0 - 1 + z, gy = y0 - 1 + y, gt = t - 1;
        uint4 v = make_uint4(0, 0, 0, 0);
        if ((unsigned)gz < 32u && (unsigned)gy < 32u && (unsigned)gt < 32u)
            v = xmh4[(gz * 1024 + gy * 32 + gt) * 16 + c];
        halo4[z * ZSC + y * YSC + t * TSC + c] = v;
    }
    for (int i = tid; i < 20; i += 256) halo4[SCRC + i] = make_uint4(0, 0, 0, 0);
    __syncthreads();

    int warp = tid >> 5, lane = tid & 31;
    int pz = warp & 1, py = (warp >> 1) & 1, th = warp >> 2;
    int g = lane >> 2, t4 = lane & 3;

    int orow  = (lane & 7) + ((lane >> 4) << 3);
    int bhalf = (lane >> 3) & 1;
    int brel[2], bsel[2];
    #pragma unroll
    for (int ng = 0; ng < 2; ng++) {
        int o = orow + ng * 16;
        if (o < 27) {
            int dz = o / 9, rr = o - dz * 9, dy = rr / 3, dx = rr - dy * 3;
            brel[ng] = dz * ZSC + dy * YSC + dx * TSC;
            bsel[ng] = 1;
        } else {
            brel[ng] = SCRC + (o - 27);
            bsel[ng] = 0;
        }
    }
    uint32_t halob = smem_u32(halo4);

    float rpbA[8], rpbB[8], wz[8], wy[8], wt[8], msk[8];
    #pragma unroll
    for (int i = 0; i < 8; i++) {
        int nt = i >> 1, j = i & 1, o = nt * 8 + 2 * t4 + j;
        if (o < 27) {
            int dz = o / 9, rr = o - dz * 9, dy = rr / 3, dx = rr - dy * 3;
            rpbA[i] = rpb_s[g * 27 + o];
            rpbB[i] = rpb_s[(g + 8) * 27 + o];
            wz[i] = (float)(dz - 1); wy[i] = (float)(dy - 1); wt[i] = (float)(dx - 1);
            msk[i] = 1.f;
        } else {
            rpbA[i] = 0.f; rpbB[i] = 0.f; wz[i] = 0.f; wy[i] = 0.f; wt[i] = 0.f; msk[i] = 0.f;
        }
    }

    const uint4* qmA4 = (const uint4*)g_qmA;
    int gp0 = (z0 + pz) * 1024 + (y0 + py) * 32 + th * 16;
    int pb0 = pz * ZSC + py * YSC + (th * 16) * TSC;

    uint4 A4[8], A4n[8];
    {
        const uint4* ap = &qmA4[((long)gp0 * 32 + lane) * 8];
        #pragma unroll
        for (int j = 0; j < 8; j++) A4[j] = ap[j];
    }

    #pragma unroll 1
    for (int i16 = 0; i16 < 16; i16++) {
        int gp = gp0 + i16;
        int pbase = pb0 + i16 * TSC;

        if (i16 < 15) {
            const uint4* ap = &qmA4[((long)(gp + 1) * 32 + lane) * 8];
            #pragma unroll
            for (int j = 0; j < 8; j++) A4n[j] = ap[j];
        }

        int basech0 = bsel[0] * pbase + brel[0] + bhalf;
        int basech1 = bsel[1] * pbase + brel[1] + bhalf;

        float acc[4][4];
        #pragma unroll
        for (int nt = 0; nt < 4; nt++)
            #pragma unroll
            for (int e = 0; e < 4; e++) acc[nt][e] = 0.f;

        const uint32_t* aw = (const uint32_t*)A4;
        #pragma unroll
        for (int kc = 0; kc < 4; kc++) {
            uint32_t bq[2][4], bq4[2][4];
            ldsm_x4(bq[0],  halob + (uint32_t)(basech0 + kc * 2) * 16u);
            ldsm_x4(bq[1],  halob + (uint32_t)(basech1 + kc * 2) * 16u);
            ldsm_x4(bq4[0], halob + (uint32_t)(basech0 + (kc + 4) * 2) * 16u);
            ldsm_x4(bq4[1], halob + (uint32_t)(basech1 + (kc + 4) * 2) * 16u);

            int u  = kc >> 1;
            int c0 = 2 * (kc & 1);
            uint32_t ah[4], al[4];
            ah[0] = aw[u * 4 + c0];           ah[1] = aw[(4 + u) * 4 + c0];
            ah[2] = aw[u * 4 + c0 + 1];       ah[3] = aw[(4 + u) * 4 + c0 + 1];
            int ul = 2 + u;
            al[0] = aw[ul * 4 + c0];          al[1] = aw[(4 + ul) * 4 + c0];
            al[2] = aw[ul * 4 + c0 + 1];      al[3] = aw[(4 + ul) * 4 + c0 + 1];
            #pragma unroll
            for (int nt = 0; nt < 4; nt++) {
                int ng = nt >> 1, hf = (nt & 1) * 2;
                mma_bf16(acc[nt], ah, bq[ng][hf],  bq[ng][hf + 1]);    // hi*hi
                mma_bf16(acc[nt], ah, bq4[ng][hf], bq4[ng][hf + 1]);   // hi*lo
                mma_bf16(acc[nt], al, bq[ng][hf],  bq[ng][hf + 1]);    // lo*hi
            }
        }

        float S0 = 0.f, Z0 = 0.f, Y0 = 0.f, T0 = 0.f;
        float S1 = 0.f, Z1 = 0.f, Y1 = 0.f, T1 = 0.f;
        #pragma unroll
        for (int i = 0; i < 8; i++) {
            int nt = i >> 1, j = i & 1;
            float e0 = __expf(acc[nt][j]     + rpbA[i]) * msk[i];
            float e1 = __expf(acc[nt][2 + j] + rpbB[i]) * msk[i];
            S0 += e0; Z0 += e0 * wz[i]; Y0 += e0 * wy[i]; T0 += e0 * wt[i];
            S1 += e1; Z1 += e1 * wz[i]; Y1 += e1 * wy[i]; T1 += e1 * wt[i];
        }
        #pragma unroll
        for (int m = 1; m < 4; m <<= 1) {
            S0 += __shfl_xor_sync(0xffffffffu, S0, m);
            Z0 += __shfl_xor_sync(0xffffffffu, Z0, m);
            Y0 += __shfl_xor_sync(0xffffffffu, Y0, m);
            T0 += __shfl_xor_sync(0xffffffffu, T0, m);
            S1 += __shfl_xor_sync(0xffffffffu, S1, m);
            Z1 += __shfl_xor_sync(0xffffffffu, Z1, m);
            Y1 += __shfl_xor_sync(0xffffffffu, Y1, m);
            T1 += __shfl_xor_sync(0xffffffffu, T1, m);
        }
        if (t4 == 0) {
            float i0 = 1.f / S0, i1 = 1.f / S1;
            out[(g * 3 + 0) * NPTS + gp] = Z0 * i0;
            out[(g * 3 + 1) * NPTS + gp] = Y0 * i0;
            out[(g * 3 + 2) * NPTS + gp] = T0 * i0;
            out[((g + 8) * 3 + 0) * NPTS + gp] = Z1 * i1;
            out[((g + 8) * 3 + 1) * NPTS + gp] = Y1 * i1;
            out[((g + 8) * 3 + 2) * NPTS + gp] = T1 * i1;
        }

        #pragma unroll
        for (int j = 0; j < 8; j++) A4[j] = A4n[j];
    }
}

// ---------------- launch ----------------
extern "C" void kernel_launch(void* const* d_in, const int* in_sizes, int n_in,
                              void* d_out, int out_size)
{
    const float* F       = (const float*)d_in[0];
    const float* M       = (const float*)d_in[1];
    const float* gamma_f = (const float*)d_in[2];
    const float* beta_f  = (const float*)d_in[3];
    const float* w_f     = (const float*)d_in[4];
    const float* b_f     = (const float*)d_in[5];
    const float* gamma_m = (const float*)d_in[6];
    const float* beta_m  = (const float*)d_in[7];
    const float* w_m     = (const float*)d_in[8];
    /* b_m (d_in[9]) is softmax-invariant and drops out */
    const float* rpb     = (const float*)d_in[10];
    float* out = (float*)d_out;

    precompute_kernel<<<16, 256>>>(w_f, w_m, b_f);
    ln_kernel<<<NPTS / 128, 128>>>(F, gamma_f, beta_f, 0);
    ln_kernel<<<NPTS / 128, 128>>>(M, gamma_m, beta_m, 1);

    cudaFuncSetAttribute(qm_gemm_mma, cudaFuncAttributeMaxDynamicSharedMemorySize, GEMM_SMEM);
    qm_gemm_mma<<<dim3(8, 64), 256, GEMM_SMEM>>>();

    cudaFuncSetAttribute(attn_kernel, cudaFuncAttributeMaxDynamicSharedMemorySize, HALO_BYTES);
    attn_kernel<<<256, 256, HALO_BYTES>>>(rpb, out);
}